// round 6
// baseline (speedup 1.0000x reference)
#include <cuda_runtime.h>
#include <cuda_bf16.h>

// BoundaryLoss fused kernel, v5: byte-packed morphology, 2x thread count.
//  - target bits packed 4-per-uint32 (1 byte/col); 5x5 box sum done in exact
//    parallel-byte integer arithmetic (max 25 < 256, no carries)
//  - horizontal window: 2 shuffles + 4 byte_perm + adds per 4 pixels
//  - vertical window: 5-register packed ring; center target: 2-register ring
//  - ROWS=8 per block -> 2048 blocks x 128 thr = 262K threads (87% of chip)
//  - last-block finalize (threadfence + ticket), double accumulation

#define BATCH 32
#define HT 512
#define WD 512
#define ROWS 8                        // output rows per block
#define ITERS (ROWS + 4)              // 12 streamed rows
#define GRID_Y (HT / ROWS)            // 64
#define NBLK (GRID_Y * BATCH)         // 2048

__device__ double g_partials[NBLK];
__device__ unsigned int g_count;      // zero-init; reset by last block each launch

// 1.0f -> 1, 0.0f -> 0 via exponent bit (2 ALU ops, no F2I)
__device__ __forceinline__ unsigned int bit01(float v) {
    return (__float_as_uint(v) >> 23) & 1u;
}

__device__ __forceinline__ void bce_w(float x, unsigned int s, unsigned int tb,
                                      float& acc) {
    // boundary iff 1 <= s <= 24  (s = exact integer box sum in [0,25])
    const float w = ((s - 1u) < 24u) ? 5.0f : 1.0f;
    const float xt = tb ? x : 0.0f;                       // t*x with t in {0,1}
    const float sp = __logf(1.0f + __expf(-fabsf(x))) + fmaxf(x, 0.0f);
    acc += (sp - xt) * w;
}

__global__ __launch_bounds__(128, 12)
void boundary_loss_kernel(const float* __restrict__ pred,
                          const float* __restrict__ target,
                          float* __restrict__ out) {
    const int tid  = threadIdx.x;        // 0..127
    const int lane = tid & 31;
    const int wid  = tid >> 5;
    const int c0   = tid * 4;            // this thread's 4 columns

    const int by = blockIdx.x;           // row-chunk (0..63)
    const int b  = blockIdx.y;           // batch     (0..31)

    const float* tgt  = target + (size_t)b * HT * WD;
    const float* pimg = pred   + (size_t)b * HT * WD;
    const int r_base = by * ROWS - 2;    // first streamed row (may be <0)

    const bool has_left  = (lane == 0)  && (c0 > 0);
    const bool has_right = (lane == 31) && (c0 + 4 < WD);

    unsigned int hr[5];                  // packed horizontal 5-sums, rows j-4..j
    unsigned int cen[2];                 // packed target bits, 2-row delay
    float acc = 0.0f;

    #pragma unroll
    for (int j = 0; j < ITERS; j++) {
        const int gr = r_base + j;
        const bool rv = (gr >= 0) && (gr < HT);
        const float* trow = tgt + (size_t)(rv ? gr : 0) * WD;

        // own 4 target values -> packed bytes [t0,t1,t2,t3]
        unsigned int tp = 0u;
        if (rv) {
            const float4 t = *(const float4*)(trow + c0);
            tp = bit01(t.x) | (bit01(t.y) << 8) |
                 (bit01(t.z) << 16) | (bit01(t.w) << 24);
        }

        // neighbor packed regs via shuffle; warp-edge lanes patch from gmem
        unsigned int up = __shfl_up_sync(0xFFFFFFFFu, tp, 1);   // [t-4..t-1]
        unsigned int dn = __shfl_down_sync(0xFFFFFFFFu, tp, 1); // [t+4..t+7]
        if (lane == 0) {
            up = 0u;
            if (rv && has_left) {
                const float2 pL = *(const float2*)(trow + c0 - 2);
                up = (bit01(pL.x) << 16) | (bit01(pL.y) << 24);
            }
        }
        if (lane == 31) {
            dn = 0u;
            if (rv && has_right) {
                const float2 pR = *(const float2*)(trow + c0 + 4);
                dn = bit01(pR.x) | (bit01(pR.y) << 8);
            }
        }

        // horizontal 5-sum per byte: cols c-2..c+2 for each of 4 columns
        const unsigned int vm2 = __byte_perm(up, tp, 0x5432); // [t-2,t-1,t0,t1]
        const unsigned int vm1 = __byte_perm(up, tp, 0x6543); // [t-1,t0,t1,t2]
        const unsigned int vp1 = __byte_perm(tp, dn, 0x4321); // [t1,t2,t3,t4]
        const unsigned int vp2 = __byte_perm(tp, dn, 0x5432); // [t2,t3,t4,t5]
        hr[j % 5] = vm2 + vm1 + tp + vp1 + vp2;               // bytes <= 5

        // center target bits, needed 2 iterations later
        const unsigned int tc = cen[j & 1];
        cen[j & 1] = tp;

        if (j >= 4) {
            // packed vertical 5-sum (bytes <= 25, exact)
            const unsigned int s = hr[0] + hr[1] + hr[2] + hr[3] + hr[4];

            const int ro = gr - 2;       // output row, always in [0, HT)
            const float4 p = *(const float4*)(pimg + (size_t)ro * WD + c0);

            bce_w(p.x,  s         & 255u,  tc        & 1u, acc);
            bce_w(p.y, (s >> 8)   & 255u, (tc >> 8)  & 1u, acc);
            bce_w(p.z, (s >> 16)  & 255u, (tc >> 16) & 1u, acc);
            bce_w(p.w,  s >> 24,           tc >> 24,       acc);
        }
    }

    // ---- block reduction: warp fp32 -> smem -> double ----
    #pragma unroll
    for (int off = 16; off > 0; off >>= 1)
        acc += __shfl_xor_sync(0xFFFFFFFFu, acc, off);

    __shared__ float s_warp[4];
    __shared__ unsigned int s_islast;
    if (lane == 0) s_warp[wid] = acc;
    __syncthreads();

    if (tid == 0) {
        double d = (double)s_warp[0] + (double)s_warp[1]
                 + (double)s_warp[2] + (double)s_warp[3];
        const int bid = blockIdx.x + GRID_Y * blockIdx.y;
        g_partials[bid] = d;
        __threadfence();
        const unsigned int ticket = atomicAdd(&g_count, 1u);
        s_islast = (ticket == NBLK - 1) ? 1u : 0u;
    }
    __syncthreads();

    // ---- last block finalizes ----
    if (s_islast) {
        const volatile double* vp = (const volatile double*)g_partials;
        double d = 0.0;
        #pragma unroll
        for (int i = 0; i < NBLK / 128; i++)
            d += vp[tid + i * 128];

        #pragma unroll
        for (int off = 16; off > 0; off >>= 1)
            d += __shfl_xor_sync(0xFFFFFFFFu, d, off);

        __shared__ double s_dw[4];
        if (lane == 0) s_dw[wid] = d;
        __syncthreads();

        if (tid == 0) {
            const double tot = s_dw[0] + s_dw[1] + s_dw[2] + s_dw[3];
            out[0] = (float)(tot / ((double)BATCH * HT * WD));
            g_count = 0;     // reset for next graph replay
        }
    }
}

extern "C" void kernel_launch(void* const* d_in, const int* in_sizes, int n_in,
                              void* d_out, int out_size) {
    const float* pred   = (const float*)d_in[0];
    const float* target = (const float*)d_in[1];
    float* out = (float*)d_out;

    dim3 grid(GRID_Y, BATCH);    // 64 x 32 = 2048 blocks
    boundary_loss_kernel<<<grid, 128>>>(pred, target, out);
}

// round 7
// speedup vs baseline: 1.1738x; 1.1738x over previous
#include <cuda_runtime.h>
#include <cuda_bf16.h>

// BoundaryLoss fused kernel, v6: v4 single-wave geometry + v5 byte-packed math.
//  - 128-thread block = full 512-px row width (4 cols/thread, float4)
//  - streams 20 rows (16 output + 4 halo), fully unrolled
//  - target bits packed 4-per-uint32; 5x5 box sum in exact parallel-byte
//    integer arithmetic (max 25 < 256); hsum = 2 shuffles + 4 PRMT + 4 IADD
//  - packed rings: vertical window 5 regs, center-target 2 regs
//    -> ~40 regs total, freeing ptxas to front-batch LDG.128s (MLP)
//  - 1024 blocks, all co-resident: exactly one wave, no quantization tail
//  - last-block finalize (threadfence + ticket), double accumulation

#define BATCH 32
#define HT 512
#define WD 512
#define ROWS 16                       // output rows per block
#define ITERS (ROWS + 4)              // 20 streamed rows
#define GRID_Y (HT / ROWS)            // 32
#define NBLK (GRID_Y * BATCH)         // 1024

__device__ double g_partials[NBLK];
__device__ unsigned int g_count;      // zero-init; reset by last block each launch

// 1.0f -> 1, 0.0f -> 0 via exponent bit (2 ALU ops, no F2I)
__device__ __forceinline__ unsigned int bit01(float v) {
    return (__float_as_uint(v) >> 23) & 1u;
}

__device__ __forceinline__ void bce_w(float x, unsigned int s, unsigned int tb,
                                      float& acc) {
    // boundary iff 1 <= s <= 24  (s = exact integer box sum in [0,25])
    const float w = ((s - 1u) < 24u) ? 5.0f : 1.0f;
    const float xt = tb ? x : 0.0f;                       // t*x with t in {0,1}
    const float sp = __logf(1.0f + __expf(-fabsf(x))) + fmaxf(x, 0.0f);
    acc += (sp - xt) * w;
}

__global__ __launch_bounds__(128, 8)
void boundary_loss_kernel(const float* __restrict__ pred,
                          const float* __restrict__ target,
                          float* __restrict__ out) {
    const int tid  = threadIdx.x;        // 0..127
    const int lane = tid & 31;
    const int wid  = tid >> 5;
    const int c0   = tid * 4;            // this thread's 4 columns

    const int by = blockIdx.x;           // row-chunk (0..31)
    const int b  = blockIdx.y;           // batch     (0..31)

    const float* tgt  = target + (size_t)b * HT * WD;
    const float* pimg = pred   + (size_t)b * HT * WD;
    const int r_base = by * ROWS - 2;    // first streamed row (may be <0)

    const bool has_left  = (lane == 0)  && (c0 > 0);
    const bool has_right = (lane == 31) && (c0 + 4 < WD);

    unsigned int hr[5];                  // packed horizontal 5-sums, rows j-4..j
    unsigned int cen[2];                 // packed target bits, 2-row delay ring
    float acc = 0.0f;

    #pragma unroll
    for (int j = 0; j < ITERS; j++) {
        const int gr = r_base + j;
        const bool rv = (gr >= 0) && (gr < HT);
        const float* trow = tgt + (size_t)(rv ? gr : 0) * WD;

        // own 4 target values -> packed bytes [t0,t1,t2,t3]
        unsigned int tp = 0u;
        if (rv) {
            const float4 t = *(const float4*)(trow + c0);
            tp = bit01(t.x) | (bit01(t.y) << 8) |
                 (bit01(t.z) << 16) | (bit01(t.w) << 24);
        }

        // neighbor packed regs via shuffle; warp-edge lanes patch from gmem
        unsigned int up = __shfl_up_sync(0xFFFFFFFFu, tp, 1);   // [t-4..t-1]
        unsigned int dn = __shfl_down_sync(0xFFFFFFFFu, tp, 1); // [t+4..t+7]
        if (lane == 0) {
            up = 0u;
            if (rv && has_left) {
                const float2 pL = *(const float2*)(trow + c0 - 2);
                up = (bit01(pL.x) << 16) | (bit01(pL.y) << 24);
            }
        }
        if (lane == 31) {
            dn = 0u;
            if (rv && has_right) {
                const float2 pR = *(const float2*)(trow + c0 + 4);
                dn = bit01(pR.x) | (bit01(pR.y) << 8);
            }
        }

        // horizontal 5-sum per byte: cols c-2..c+2 for each of 4 columns
        const unsigned int vm2 = __byte_perm(up, tp, 0x5432); // [t-2,t-1,t0,t1]
        const unsigned int vm1 = __byte_perm(up, tp, 0x6543); // [t-1,t0,t1,t2]
        const unsigned int vp1 = __byte_perm(tp, dn, 0x4321); // [t1,t2,t3,t4]
        const unsigned int vp2 = __byte_perm(tp, dn, 0x5432); // [t2,t3,t4,t5]
        hr[j % 5] = vm2 + vm1 + tp + vp1 + vp2;               // bytes <= 5

        // center target bits, needed 2 iterations later
        const unsigned int tc = cen[j & 1];
        cen[j & 1] = tp;

        if (j >= 4) {
            // packed vertical 5-sum (bytes <= 25, exact)
            const unsigned int s = hr[0] + hr[1] + hr[2] + hr[3] + hr[4];

            const int ro = gr - 2;       // output row, always in [0, HT)
            const float4 p = *(const float4*)(pimg + (size_t)ro * WD + c0);

            bce_w(p.x,  s         & 255u,  tc        & 1u, acc);
            bce_w(p.y, (s >> 8)   & 255u, (tc >> 8)  & 1u, acc);
            bce_w(p.z, (s >> 16)  & 255u, (tc >> 16) & 1u, acc);
            bce_w(p.w,  s >> 24,           tc >> 24,       acc);
        }
    }

    // ---- block reduction: warp fp32 -> smem -> double ----
    #pragma unroll
    for (int off = 16; off > 0; off >>= 1)
        acc += __shfl_xor_sync(0xFFFFFFFFu, acc, off);

    __shared__ float s_warp[4];
    __shared__ unsigned int s_islast;
    if (lane == 0) s_warp[wid] = acc;
    __syncthreads();

    if (tid == 0) {
        double d = (double)s_warp[0] + (double)s_warp[1]
                 + (double)s_warp[2] + (double)s_warp[3];
        const int bid = blockIdx.x + GRID_Y * blockIdx.y;
        g_partials[bid] = d;
        __threadfence();
        const unsigned int ticket = atomicAdd(&g_count, 1u);
        s_islast = (ticket == NBLK - 1) ? 1u : 0u;
    }
    __syncthreads();

    // ---- last block finalizes ----
    if (s_islast) {
        const volatile double* vp = (const volatile double*)g_partials;
        double d = 0.0;
        #pragma unroll
        for (int i = 0; i < NBLK / 128; i++)
            d += vp[tid + i * 128];

        #pragma unroll
        for (int off = 16; off > 0; off >>= 1)
            d += __shfl_xor_sync(0xFFFFFFFFu, d, off);

        __shared__ double s_dw[4];
        if (lane == 0) s_dw[wid] = d;
        __syncthreads();

        if (tid == 0) {
            const double tot = s_dw[0] + s_dw[1] + s_dw[2] + s_dw[3];
            out[0] = (float)(tot / ((double)BATCH * HT * WD));
            g_count = 0;     // reset for next graph replay
        }
    }
}

extern "C" void kernel_launch(void* const* d_in, const int* in_sizes, int n_in,
                              void* d_out, int out_size) {
    const float* pred   = (const float*)d_in[0];
    const float* target = (const float*)d_in[1];
    float* out = (float*)d_out;

    dim3 grid(GRID_Y, BATCH);    // 32 x 32 = 1024 blocks, single clean wave
    boundary_loss_kernel<<<grid, 128>>>(pred, target, out);
}

// round 8
// speedup vs baseline: 1.4419x; 1.2285x over previous
#include <cuda_runtime.h>
#include <cuda_bf16.h>

// BoundaryLoss fused kernel, v7: v4 geometry, shuffle-free horizontal halo.
//  - 128-thread block = full 512-px row width (4 cols/thread, float4)
//  - streams 20 rows (16 output + 4 halo), fully unrolled
//  - horizontal neighbors via overlapping float2 loads (same cache lines,
//    no SHFL sync points) -> all loads independent, deep MLP
//  - vertical 5-sum as exact running window (+new -old)
//  - 1024 blocks, all co-resident: one clean wave
//  - last-block finalize (threadfence + ticket), double accumulation

#define BATCH 32
#define HT 512
#define WD 512
#define ROWS 16                       // output rows per block
#define ITERS (ROWS + 4)              // 20 streamed rows
#define GRID_Y (HT / ROWS)            // 32
#define NBLK (GRID_Y * BATCH)         // 1024

__device__ double g_partials[NBLK];
__device__ unsigned int g_count;      // zero-init; reset by last block each launch

__device__ __forceinline__ void bce_w(float x, float t, float s, float& acc) {
    // weight: 5 inside boundary band (0 < boxsum < 25), else 1 (boxsum exact int)
    const float w = (s > 0.5f && s < 24.5f) ? 5.0f : 1.0f;
    // BCE(sigmoid(x), t) = softplus(x) - t*x; stable fast-math softplus
    const float sp = __logf(1.0f + __expf(-fabsf(x))) + fmaxf(x, 0.0f);
    acc = fmaf(fmaf(-x, t, sp), w, acc);
}

__global__ __launch_bounds__(128, 8)
void boundary_loss_kernel(const float* __restrict__ pred,
                          const float* __restrict__ target,
                          float* __restrict__ out) {
    const int tid  = threadIdx.x;        // 0..127
    const int lane = tid & 31;
    const int wid  = tid >> 5;
    const int c0   = tid * 4;            // this thread's 4 columns

    const int by = blockIdx.x;           // row-chunk (0..31)
    const int b  = blockIdx.y;           // batch     (0..31)

    const float* tgt  = target + (size_t)b * HT * WD;
    const float* pimg = pred   + (size_t)b * HT * WD;
    const int r_base = by * ROWS - 2;    // first streamed row (may be <0)

    const bool has_left  = (c0 > 0);           // false only for tid 0
    const bool has_right = (c0 + 4 < WD);      // false only for tid 127

    float4 hring[5];                     // horizontal 5-sums, rows j-4..j
    float4 cen[2];                       // center target quad, 2-row delay ring
    float4 vs = make_float4(0.f, 0.f, 0.f, 0.f);
    float acc = 0.0f;

    #pragma unroll
    for (int j = 0; j < ITERS; j++) {
        const int gr = r_base + j;
        const bool rv = (gr >= 0) && (gr < HT);
        const float* trow = tgt + (size_t)(rv ? gr : 0) * WD;

        // 3 independent loads per row: own quad + 2-wide halo on each side.
        // Halo loads hit the 128B lines the warp already fetches (L1/L2).
        float4 t  = make_float4(0.f, 0.f, 0.f, 0.f);
        float2 tL = make_float2(0.f, 0.f);
        float2 tR = make_float2(0.f, 0.f);
        if (rv)              t  = *(const float4*)(trow + c0);
        if (rv && has_left)  tL = *(const float2*)(trow + c0 - 2);  // 8B aligned
        if (rv && has_right) tR = *(const float2*)(trow + c0 + 4);

        // horizontal 5-sums (CSE'd, 9 FADD; exact small-int arithmetic)
        const float a3 = t.x + t.y + t.z;
        const float a4 = a3 + t.w;
        float4 h;
        h.x = tL.x + tL.y + a3;
        h.y = tL.y + a4;
        h.z = a4 + tR.x;
        h.w = (h.z - t.x) + tR.y;

        // vertical running 5-window (exact: all terms small integers)
        if (j >= 5) {
            const float4 ho = hring[j % 5];
            vs.x -= ho.x; vs.y -= ho.y; vs.z -= ho.z; vs.w -= ho.w;
        }
        vs.x += h.x; vs.y += h.y; vs.z += h.z; vs.w += h.w;
        hring[j % 5] = h;

        // center target quad, needed 2 iterations later
        const float4 tc = cen[j & 1];
        cen[j & 1] = t;

        if (j >= 4) {
            const int ro = gr - 2;       // output row, always in [0, HT)
            const float4 p = *(const float4*)(pimg + (size_t)ro * WD + c0);
            bce_w(p.x, tc.x, vs.x, acc);
            bce_w(p.y, tc.y, vs.y, acc);
            bce_w(p.z, tc.z, vs.z, acc);
            bce_w(p.w, tc.w, vs.w, acc);
        }
    }

    // ---- block reduction: warp fp32 -> smem -> double ----
    #pragma unroll
    for (int off = 16; off > 0; off >>= 1)
        acc += __shfl_xor_sync(0xFFFFFFFFu, acc, off);

    __shared__ float s_warp[4];
    __shared__ unsigned int s_islast;
    if (lane == 0) s_warp[wid] = acc;
    __syncthreads();

    if (tid == 0) {
        double d = (double)s_warp[0] + (double)s_warp[1]
                 + (double)s_warp[2] + (double)s_warp[3];
        const int bid = blockIdx.x + GRID_Y * blockIdx.y;
        g_partials[bid] = d;
        __threadfence();
        const unsigned int ticket = atomicAdd(&g_count, 1u);
        s_islast = (ticket == NBLK - 1) ? 1u : 0u;
    }
    __syncthreads();

    // ---- last block finalizes ----
    if (s_islast) {
        const volatile double* vp = (const volatile double*)g_partials;
        double d = 0.0;
        #pragma unroll
        for (int i = 0; i < NBLK / 128; i++)
            d += vp[tid + i * 128];

        #pragma unroll
        for (int off = 16; off > 0; off >>= 1)
            d += __shfl_xor_sync(0xFFFFFFFFu, d, off);

        __shared__ double s_dw[4];
        if (lane == 0) s_dw[wid] = d;
        __syncthreads();

        if (tid == 0) {
            const double tot = s_dw[0] + s_dw[1] + s_dw[2] + s_dw[3];
            out[0] = (float)(tot / ((double)BATCH * HT * WD));
            g_count = 0;     // reset for next graph replay
        }
    }
}

extern "C" void kernel_launch(void* const* d_in, const int* in_sizes, int n_in,
                              void* d_out, int out_size) {
    const float* pred   = (const float*)d_in[0];
    const float* target = (const float*)d_in[1];
    float* out = (float*)d_out;

    dim3 grid(GRID_Y, BATCH);    // 32 x 32 = 1024 blocks, single clean wave
    boundary_loss_kernel<<<grid, 128>>>(pred, target, out);
}